// round 1
// baseline (speedup 1.0000x reference)
#include <cuda_runtime.h>
#include <math.h>

// Problem constants (fixed shapes)
#define Bq   4
#define Nq   65536
#define Gq   64
#define G3q  262144          // 64^3
#define CF   32
#define HW   128
#define VSC  0.05f
#define R2C  1.5625f         // 1.25^2

// -------- device scratch (no allocations allowed) --------
__device__ float         g_P[(size_t)Bq * HW * HW * 64];   // 16 MB projected feature map
__device__ unsigned char g_occ[(size_t)Bq * G3q];          // 1 MB occupancy
__device__ int           g_anyNearby[Bq];
__device__ int           g_anyOcc[Bq];
__device__ float         g_accum[Bq][8];                   // w, w*px, w*py, w*pz, px, py, pz

// ---------------------------------------------------------
__global__ void k_clear() {
    int i = blockIdx.x * blockDim.x + threadIdx.x;
    if (i < G3q) ((int*)g_occ)[i] = 0;   // Bq*G3q bytes == G3q ints
    if (i < Bq) { g_anyNearby[i] = 0; g_anyOcc[i] = 0; }
    if (i < Bq * 8) ((float*)g_accum)[i] = 0.0f;
}

__device__ __forceinline__ bool is_nearby(float px, float py, float pz,
                                          float ax, float ay, float az) {
    float dx = px - ax, dy = py - ay;
    float d2xy = dx * dx + dy * dy;
    float e0 = pz - (az - 0.5f);
    float e1 = pz - az;
    float e2 = pz - (az + 0.5f);
    float m = fminf(fminf(e0 * e0, e1 * e1), e2 * e2);
    return (d2xy + m) <= R2C;
}

// pass A: does any point lie near the anchors (per batch)?
__global__ void k_nearby(const float* __restrict__ points,
                         const float* __restrict__ pelvis) {
    int idx = blockIdx.x * blockDim.x + threadIdx.x;   // B*N threads
    int b = idx >> 16;                                 // N = 65536
    float ax = pelvis[b * 3 + 0], ay = pelvis[b * 3 + 1], az = pelvis[b * 3 + 2];
    float px = points[(size_t)idx * 3 + 0];
    float py = points[(size_t)idx * 3 + 1];
    float pz = points[(size_t)idx * 3 + 2];
    bool nb = is_nearby(px, py, pz, ax, ay, az);
    unsigned m = __ballot_sync(0xffffffffu, nb);
    if ((threadIdx.x & 31) == 0 && m) atomicOr(&g_anyNearby[b], 1);
}

// pass B: scatter occupancy
__global__ void k_scatter(const float* __restrict__ points,
                          const float* __restrict__ pelvis) {
    int idx = blockIdx.x * blockDim.x + threadIdx.x;
    int b = idx >> 16;
    float ax = pelvis[b * 3 + 0], ay = pelvis[b * 3 + 1], az = pelvis[b * 3 + 2];
    float px = points[(size_t)idx * 3 + 0];
    float py = points[(size_t)idx * 3 + 1];
    float pz = points[(size_t)idx * 3 + 2];
    bool nb = is_nearby(px, py, pz, ax, ay, az);
    if (!g_anyNearby[b]) nb = true;   // fallback: if nothing nearby, keep all

    int v0x = (int)floorf(ax / VSC) - (Gq / 2);
    int v0y = (int)floorf(ay / VSC) - (Gq / 2);
    int v0z = (int)floorf(az / VSC) - (Gq / 2);
    int lx = (int)floorf(px / VSC) - v0x;
    int ly = (int)floorf(py / VSC) - v0y;
    int lz = (int)floorf(pz / VSC) - v0z;
    bool inb = nb && (unsigned)lx < (unsigned)Gq && (unsigned)ly < (unsigned)Gq
                  && (unsigned)lz < (unsigned)Gq;
    if (inb) g_occ[(size_t)b * G3q + ((lx << 12) + (ly << 6) + lz)] = 1;
    unsigned m = __ballot_sync(0xffffffffu, inb);
    if ((threadIdx.x & 31) == 0 && m) atomicOr(&g_anyOcc[b], 1);
}

// Precompute P[b,y,x,j] = sum_c fmap[b,c,y,x] * W1[3+c, j]
__global__ void __launch_bounds__(256) k_proj(const float* __restrict__ fmap,
                                              const float* __restrict__ W1) {
    int idx = blockIdx.x * 256 + threadIdx.x;   // B*HW*HW*64 threads
    int j   = idx & 63;
    int rest = idx >> 6;
    int pix = rest & (HW * HW - 1);
    int b   = rest >> 14;
    const float* fp = fmap + (size_t)b * CF * HW * HW + pix;
    float a = 0.0f;
#pragma unroll
    for (int c = 0; c < CF; ++c)
        a = fmaf(__ldg(fp + c * HW * HW), W1[(3 + c) * 64 + j], a);
    g_P[(size_t)idx] = a;
}

// Main per-voxel kernel: project center -> bilinear on P -> relu -> W2 -> out[12]
// Also accumulates softmax-weighted refinement (shift-free exp trick).
__global__ void __launch_bounds__(256) k_main(const float* __restrict__ pelvis,
                                              const float* __restrict__ Kmat,
                                              const float* __restrict__ bbx,
                                              const float* __restrict__ W1,
                                              const float* __restrict__ b1,
                                              const float* __restrict__ W2,
                                              const float* __restrict__ b2,
                                              float* __restrict__ outp) {
    __shared__ float4 sW1g[64];     // (W1[0,j], W1[1,j], W1[2,j], b1[j])
    __shared__ float  sW2[768];     // W2 row-major [j][o]
    __shared__ float  sB2[12];
    __shared__ float  sred[8][7];

    int t = threadIdx.x;
    if (t < 64) sW1g[t] = make_float4(W1[t], W1[64 + t], W1[128 + t], b1[t]);
    for (int i = t; i < 768; i += 256) sW2[i] = W2[i];
    if (t < 12) sB2[t] = b2[t];
    __syncthreads();

    int b = blockIdx.y;
    int g = blockIdx.x * 256 + t;

    float ax = pelvis[b * 3 + 0], ay = pelvis[b * 3 + 1], az = pelvis[b * 3 + 2];
    int v0x = (int)floorf(ax / VSC) - (Gq / 2);
    int v0y = (int)floorf(ay / VSC) - (Gq / 2);
    int v0z = (int)floorf(az / VSC) - (Gq / 2);

    int gx = g >> 12, gy = (g >> 6) & 63, gz = g & 63;
    float cxv = (float)(v0x + gx) * VSC + VSC * 0.5f;
    float cyv = (float)(v0y + gy) * VSC + VSC * 0.5f;
    float czv = (float)(v0z + gz) * VSC + VSC * 0.5f;

    float fx = Kmat[b * 9 + 0], cx0 = Kmat[b * 9 + 2];
    float fy = Kmat[b * 9 + 4], cy0 = Kmat[b * 9 + 5];
    float l = bbx[b * 4 + 0], tp = bbx[b * 4 + 1];
    float r = bbx[b * 4 + 2], bt = bbx[b * 4 + 3];

    float u  = cxv / czv * fx + cx0;
    float vp = cyv / czv * fy + cy0;
    float U = (u - l) / (r - l) * (float)(HW - 1);
    float V = (vp - tp) / (bt - tp) * (float)(HW - 1);

    float x0f = floorf(U), y0f = floorf(V);
    float wx = U - x0f, wy = V - y0f;
    int x0 = (int)x0f, y0 = (int)y0f;
    int x1 = x0 + 1, y1 = y0 + 1;
    bool okx0 = (x0 >= 0 && x0 <= HW - 1), okx1 = (x1 >= 0 && x1 <= HW - 1);
    bool oky0 = (y0 >= 0 && y0 <= HW - 1), oky1 = (y1 >= 0 && y1 <= HW - 1);
    int x0c = min(max(x0, 0), HW - 1), x1c = min(max(x1, 0), HW - 1);
    int y0c = min(max(y0, 0), HW - 1), y1c = min(max(y1, 0), HW - 1);

    float w00 = (1.0f - wx) * (1.0f - wy) * ((okx0 && oky0) ? 1.0f : 0.0f);
    float w10 = wx * (1.0f - wy)          * ((okx1 && oky0) ? 1.0f : 0.0f);
    float w01 = (1.0f - wx) * wy          * ((okx0 && oky1) ? 1.0f : 0.0f);
    float w11 = wx * wy                   * ((okx1 && oky1) ? 1.0f : 0.0f);

    const float* Pb = g_P + (size_t)b * (HW * HW * 64);
    const float4* p00 = (const float4*)(Pb + ((y0c * HW + x0c) << 6));
    const float4* p10 = (const float4*)(Pb + ((y0c * HW + x1c) << 6));
    const float4* p01 = (const float4*)(Pb + ((y1c * HW + x0c) << 6));
    const float4* p11 = (const float4*)(Pb + ((y1c * HW + x1c) << 6));

    float geox = ax - cxv, geoy = ay - cyv, geoz = az - czv;

    float acc[12];
#pragma unroll
    for (int o = 0; o < 12; ++o) acc[o] = sB2[o];

#pragma unroll 4
    for (int j4 = 0; j4 < 16; ++j4) {
        float4 t00 = p00[j4], t10 = p10[j4], t01 = p01[j4], t11 = p11[j4];
        float samp[4];
        samp[0] = fmaf(w00, t00.x, fmaf(w10, t10.x, fmaf(w01, t01.x, w11 * t11.x)));
        samp[1] = fmaf(w00, t00.y, fmaf(w10, t10.y, fmaf(w01, t01.y, w11 * t11.y)));
        samp[2] = fmaf(w00, t00.z, fmaf(w10, t10.z, fmaf(w01, t01.z, w11 * t11.z)));
        samp[3] = fmaf(w00, t00.w, fmaf(w10, t10.w, fmaf(w01, t01.w, w11 * t11.w)));
#pragma unroll
        for (int k = 0; k < 4; ++k) {
            int j = j4 * 4 + k;
            float4 wg = sW1g[j];
            float h = fmaf(geox, wg.x, fmaf(geoy, wg.y, fmaf(geoz, wg.z, wg.w))) + samp[k];
            h = fmaxf(h, 0.0f);
            const float4* w2r = (const float4*)(&sW2[j * 12]);
            float4 wa = w2r[0], wb = w2r[1], wc = w2r[2];
            acc[0] = fmaf(h, wa.x, acc[0]);  acc[1] = fmaf(h, wa.y, acc[1]);
            acc[2] = fmaf(h, wa.z, acc[2]);  acc[3] = fmaf(h, wa.w, acc[3]);
            acc[4] = fmaf(h, wb.x, acc[4]);  acc[5] = fmaf(h, wb.y, acc[5]);
            acc[6] = fmaf(h, wb.z, acc[6]);  acc[7] = fmaf(h, wb.w, acc[7]);
            acc[8] = fmaf(h, wc.x, acc[8]);  acc[9] = fmaf(h, wc.y, acc[9]);
            acc[10] = fmaf(h, wc.z, acc[10]); acc[11] = fmaf(h, wc.w, acc[11]);
        }
    }

    // write out[b, g, 0:12]
    float4* op = (float4*)(outp + ((size_t)b * G3q + g) * 12);
    op[0] = make_float4(acc[0], acc[1], acc[2], acc[3]);
    op[1] = make_float4(acc[4], acc[5], acc[6], acc[7]);
    op[2] = make_float4(acc[8], acc[9], acc[10], acc[11]);

    // softmax contributions: s = sigmoid(conf) in (0,1); exp(s) safe, shift-invariant.
    unsigned char occv = g_occ[(size_t)b * G3q + g];
    float sg  = 1.0f / (1.0f + expf(-acc[0]));
    float wgt = occv ? expf(sg) : 0.0f;
    float px = cxv + acc[1], py = cyv + acc[2], pz = czv + acc[3];

    float red7[7] = { wgt, wgt * px, wgt * py, wgt * pz, px, py, pz };
#pragma unroll
    for (int i = 0; i < 7; ++i) {
        float v = red7[i];
        v += __shfl_down_sync(0xffffffffu, v, 16);
        v += __shfl_down_sync(0xffffffffu, v, 8);
        v += __shfl_down_sync(0xffffffffu, v, 4);
        v += __shfl_down_sync(0xffffffffu, v, 2);
        v += __shfl_down_sync(0xffffffffu, v, 1);
        red7[i] = v;
    }
    int wid = t >> 5, lane = t & 31;
    if (lane == 0) {
#pragma unroll
        for (int i = 0; i < 7; ++i) sred[wid][i] = red7[i];
    }
    __syncthreads();
    if (t < 7) {
        float s = 0.0f;
#pragma unroll
        for (int w = 0; w < 8; ++w) s += sred[w][t];
        atomicAdd(&g_accum[b][t], s);
    }
}

__global__ void k_finalize(const float* __restrict__ pelvis,
                           float* __restrict__ refined) {
    int b = threadIdx.x;
    if (b >= Bq) return;
    float wsum = g_accum[b][0];
    float x, y, z;
    if (g_anyOcc[b]) {
        x = g_accum[b][1] / wsum;
        y = g_accum[b][2] / wsum;
        z = g_accum[b][3] / wsum;
    } else {                      // uniform softmax over all voxels
        x = g_accum[b][4] / (float)G3q;
        y = g_accum[b][5] / (float)G3q;
        z = g_accum[b][6] / (float)G3q;
    }
    bool bad = isnan(x) || isnan(y) || isnan(z);
    refined[b * 3 + 0] = bad ? pelvis[b * 3 + 0] : x;
    refined[b * 3 + 1] = bad ? pelvis[b * 3 + 1] : y;
    refined[b * 3 + 2] = bad ? pelvis[b * 3 + 2] : z;
}

extern "C" void kernel_launch(void* const* d_in, const int* in_sizes, int n_in,
                              void* d_out, int out_size) {
    const float* points = (const float*)d_in[0];
    const float* fmap   = (const float*)d_in[1];
    const float* pelvis = (const float*)d_in[2];
    const float* Kmat   = (const float*)d_in[3];
    const float* bbx    = (const float*)d_in[4];
    const float* W1     = (const float*)d_in[5];
    const float* b1     = (const float*)d_in[6];
    const float* W2     = (const float*)d_in[7];
    const float* b2     = (const float*)d_in[8];

    float* refined = (float*)d_out;          // (B,3) first
    float* outp    = (float*)d_out + Bq * 3; // (B,G3,12) second

    k_clear<<<(G3q + 255) / 256, 256>>>();
    k_proj<<<(Bq * HW * HW * 64) / 256, 256>>>(fmap, W1);
    k_nearby<<<(Bq * Nq) / 256, 256>>>(points, pelvis);
    k_scatter<<<(Bq * Nq) / 256, 256>>>(points, pelvis);
    k_main<<<dim3(G3q / 256, Bq), 256>>>(pelvis, Kmat, bbx, W1, b1, W2, b2, outp);
    k_finalize<<<1, 32>>>(pelvis, refined);
}